// round 15
// baseline (speedup 1.0000x reference)
#include <cuda_runtime.h>
#include <cuda_fp16.h>
#include <cstdint>

#define B_   8
#define S_   2048
#define D_   128
#define ROWS (B_*S_)            // 16384
#define QSCALE 0.18033688011112042f   // log2(e)/8

// ---------------- scratch (static device memory; no allocation) -------------
__device__ __half g_qk_h[ROWS*D_];          // LN(x+emb) f16
__device__ __half g_v_h [ROWS*D_];          // LN(x) f16
__device__ __half g_q[16*S_*64];            // (b,h,s,dh), pre-scaled by log2e/8
__device__ __half g_k[16*S_*64];            // (b,h,s,dh)
__device__ __half g_v[16*S_*64];            // (b,h,s,dh)  (trans-loaded in attn)
__device__ __half g_ctx_h[ROWS*D_];         // attention out, f16
__device__ uint32_t g_mask[S_*64];          // pair mask bits: [q][k>>5] bit (k&31)
__device__ __half g_wh[131072];             // f16 weights: qkv | out | l1 | l2

#define WOFF_QKV 0
#define WOFF_O   49152
#define WOFF_1   65536
#define WOFF_2   98304

// ---------------- helpers ----------------------------------------------------
__device__ __forceinline__ uint32_t pack_f16(float hi, float lo) {
    uint32_t d;
    asm("cvt.rn.f16x2.f32 %0, %1, %2;" : "=r"(d) : "f"(hi), "f"(lo));
    return d;
}
__device__ __forceinline__ uint32_t ex2h2(uint32_t x) {
    asm("ex2.approx.f16x2 %0, %0;" : "+r"(x));
    return x;
}
__device__ __forceinline__ void mma_f16(float* d, uint32_t a0, uint32_t a1,
                                        uint32_t a2, uint32_t a3,
                                        uint32_t b0, uint32_t b1) {
    asm volatile("mma.sync.aligned.m16n8k16.row.col.f32.f16.f16.f32 "
        "{%0,%1,%2,%3}, {%4,%5,%6,%7}, {%8,%9}, {%0,%1,%2,%3};"
        : "+f"(d[0]), "+f"(d[1]), "+f"(d[2]), "+f"(d[3])
        : "r"(a0), "r"(a1), "r"(a2), "r"(a3), "r"(b0), "r"(b1));
}
__device__ __forceinline__ void ldsm4(uint32_t& r0, uint32_t& r1,
                                      uint32_t& r2, uint32_t& r3,
                                      const void* p) {
    uint32_t a = (uint32_t)__cvta_generic_to_shared(p);
    asm volatile("ldmatrix.sync.aligned.m8n8.x4.shared.b16 {%0,%1,%2,%3}, [%4];"
        : "=r"(r0), "=r"(r1), "=r"(r2), "=r"(r3) : "r"(a));
}
__device__ __forceinline__ void ldsm4_t(uint32_t& r0, uint32_t& r1,
                                        uint32_t& r2, uint32_t& r3,
                                        const void* p) {
    uint32_t a = (uint32_t)__cvta_generic_to_shared(p);
    asm volatile("ldmatrix.sync.aligned.m8n8.x4.trans.shared.b16 {%0,%1,%2,%3}, [%4];"
        : "=r"(r0), "=r"(r1), "=r"(r2), "=r"(r3) : "r"(a));
}
__device__ __forceinline__ void cpa16(void* sdst, const void* gsrc) {
    uint32_t s = (uint32_t)__cvta_generic_to_shared(sdst);
    asm volatile("cp.async.cg.shared.global [%0], [%1], 16;"
                 :: "r"(s), "l"(gsrc) : "memory");
}
#define CP_COMMIT() asm volatile("cp.async.commit_group;" ::: "memory")
#define CP_WAIT0()  asm volatile("cp.async.wait_group 0;" ::: "memory")

// ---------------- fused setup: weight cvt + mask bitmatrix + dual LN ---------
// grid 2432: [0,2048) ln, [2048,2304) mask, [2304,2432) weight cvt
__global__ void __launch_bounds__(256) setup_kernel(
    const float* __restrict__ x, const float* __restrict__ emb,
    const float* __restrict__ lng, const float* __restrict__ lnb,
    const int* __restrict__ nodeT,
    const float* __restrict__ wqkv, const float* __restrict__ wo,
    const float* __restrict__ w1,   const float* __restrict__ w2)
{
    __shared__ int smac[2048];
    __shared__ int sjob[2048];
    int bid = blockIdx.x;
    int tid = threadIdx.x;

    if (bid < 2048) {
        int row  = bid * 8 + (tid >> 5);
        int lane = tid & 31;
        size_t base = (size_t)row * 32 + lane;

        float4 xv = ((const float4*)x)[base];
        float4 ev = ((const float4*)emb)[base];
        float4 g4 = ((const float4*)lng)[lane];
        float4 b4 = ((const float4*)lnb)[lane];

        float4 t = make_float4(xv.x+ev.x, xv.y+ev.y, xv.z+ev.z, xv.w+ev.w);
        float s = t.x + t.y + t.z + t.w;
        #pragma unroll
        for (int o = 16; o; o >>= 1) s += __shfl_xor_sync(0xffffffffu, s, o);
        float mu = s * (1.0f/128.0f);
        float dx = t.x-mu, dy = t.y-mu, dz = t.z-mu, dw = t.w-mu;
        float v2 = dx*dx + dy*dy + dz*dz + dw*dw;
        #pragma unroll
        for (int o = 16; o; o >>= 1) v2 += __shfl_xor_sync(0xffffffffu, v2, o);
        float r = rsqrtf(v2 * (1.0f/128.0f) + 1e-5f);
        ((uint2*)g_qk_h)[base] = make_uint2(
            pack_f16(dy*r*g4.y + b4.y, dx*r*g4.x + b4.x),
            pack_f16(dw*r*g4.w + b4.w, dz*r*g4.z + b4.z));

        s = xv.x + xv.y + xv.z + xv.w;
        #pragma unroll
        for (int o = 16; o; o >>= 1) s += __shfl_xor_sync(0xffffffffu, s, o);
        mu = s * (1.0f/128.0f);
        dx = xv.x-mu; dy = xv.y-mu; dz = xv.z-mu; dw = xv.w-mu;
        v2 = dx*dx + dy*dy + dz*dz + dw*dw;
        #pragma unroll
        for (int o = 16; o; o >>= 1) v2 += __shfl_xor_sync(0xffffffffu, v2, o);
        r = rsqrtf(v2 * (1.0f/128.0f) + 1e-5f);
        ((uint2*)g_v_h)[base] = make_uint2(
            pack_f16(dy*r*g4.y + b4.y, dx*r*g4.x + b4.x),
            pack_f16(dw*r*g4.w + b4.w, dz*r*g4.z + b4.z));
    } else if (bid < 2304) {
        for (int i = tid; i < 2048; i += 256) {
            smac[i] = nodeT[i*3 + 2];
            sjob[i] = nodeT[i*3 + 0];
        }
        __syncthreads();
        int w = tid >> 5, lane = tid & 31;
        int qr = (bid - 2048) * 8 + w;
        int mq = smac[qr], jq = sjob[qr];
        for (int wd = 0; wd < 64; wd++) {
            int kk = wd*32 + lane;
            int bit = (mq != smac[kk]) & (jq != sjob[kk]);
            uint32_t word = __ballot_sync(0xffffffffu, bit);
            if (lane == 0) g_mask[qr*64 + wd] = word;
        }
    } else {
        int i = ((bid - 2304)*256 + tid) * 4;
        const float* src; int off;
        if (i < 49152)       { src = wqkv; off = i; }
        else if (i < 65536)  { src = wo;   off = i - 49152; }
        else if (i < 98304)  { src = w1;   off = i - 65536; }
        else                 { src = w2;   off = i - 98304; }
        float4 t = *(const float4*)(src + off);
        *(uint2*)&g_wh[i] = make_uint2(pack_f16(t.y, t.x), pack_f16(t.w, t.z));
    }
}

// ================= f16 QKV GEMM ==============================================
__global__ void __launch_bounds__(256, 2) qkv_gemm(
    const __half* __restrict__ A, const __half* __restrict__ A2,
    const __half* __restrict__ W, const float* __restrict__ bias,
    __half* __restrict__ p0, __half* __restrict__ p1, __half* __restrict__ p2)
{
    extern __shared__ uint4 dsm[];
    uint4* As = dsm;          // [2][1024]
    uint4* Ws = dsm + 2048;   // [2][1024]

    const int K = 128;
    int m0 = blockIdx.x * 128, n0 = blockIdx.y * 128;
    int tid = threadIdx.x;
    int w = tid >> 5, lane = tid & 31, g = lane >> 2, tg = lane & 3;
    int wm = w >> 1, wn = w & 1;

    const __half* Asrc = (blockIdx.y == 2) ? A2 : A;

    float c[2][8][4];
    #pragma unroll
    for (int mt = 0; mt < 2; mt++)
        #pragma unroll
        for (int j = 0; j < 8; j++)
            #pragma unroll
            for (int i = 0; i < 4; i++) c[mt][j][i] = 0.f;

    #pragma unroll
    for (int it = 0; it < 4; it++) {
        int i = tid + 256*it;
        int r = i >> 3, cc = i & 7;
        int sd = r*8 + (cc ^ (r & 7));
        cpa16(&As[sd], Asrc + (size_t)(m0 + r)*K + cc*8);
        cpa16(&Ws[sd], W    + (size_t)(n0 + r)*K + cc*8);
    }
    CP_COMMIT();

    int la15 = lane & 15, xq = lane & 7, cbq = lane >> 4;
    int rowk = (lane & 7) + 8*(lane >> 4);
    int cbk  = (lane >> 3) & 1;
    int xk   = rowk & 7;

    for (int ic = 0; ic < 2; ic++) {
        CP_WAIT0();
        __syncthreads();
        int cur = ic & 1;
        if (ic == 0) {
            #pragma unroll
            for (int it = 0; it < 4; it++) {
                int i = tid + 256*it;
                int r = i >> 3, cc = i & 7;
                int sd = 1024 + r*8 + (cc ^ (r & 7));
                cpa16(&As[sd], Asrc + (size_t)(m0 + r)*K + 64 + cc*8);
                cpa16(&Ws[sd], W    + (size_t)(n0 + r)*K + 64 + cc*8);
            }
            CP_COMMIT();
        }
        const uint4* Ac = As + cur*1024;
        const uint4* Wc = Ws + cur*1024;

        #pragma unroll
        for (int ks = 0; ks < 4; ks++) {
            uint32_t a[2][4];
            #pragma unroll
            for (int mt = 0; mt < 2; mt++)
                ldsm4(a[mt][0], a[mt][1], a[mt][2], a[mt][3],
                      Ac + (32*wm + 16*mt + la15)*8 + ((2*ks + cbq) ^ xq));
            int ck = (2*ks + cbk) ^ xk;
            #pragma unroll
            for (int J = 0; J < 4; J++) {
                uint32_t b0, b1, b2, b3;
                ldsm4(b0, b1, b2, b3, Wc + (64*wn + J*16 + rowk)*8 + ck);
                #pragma unroll
                for (int mt = 0; mt < 2; mt++) {
                    mma_f16(c[mt][2*J],   a[mt][0], a[mt][1], a[mt][2], a[mt][3], b0, b1);
                    mma_f16(c[mt][2*J+1], a[mt][0], a[mt][1], a[mt][2], a[mt][3], b2, b3);
                }
            }
        }
    }

    #pragma unroll
    for (int mt = 0; mt < 2; mt++) {
        int r0 = m0 + 32*wm + 16*mt + g;
        int r1 = r0 + 8;
        #pragma unroll
        for (int j = 0; j < 8; j++) {
            int n = n0 + 64*wn + 8*j + 2*tg;
            float2 bs = *(const float2*)(bias + n);
            float v00 = c[mt][j][0] + bs.x, v01 = c[mt][j][1] + bs.y;
            float v10 = c[mt][j][2] + bs.x, v11 = c[mt][j][3] + bs.y;
            int b0i = r0 >> 11, s0i = r0 & 2047;
            int b1i = r1 >> 11, s1i = r1 & 2047;
            float sc = (n < 128) ? QSCALE : 1.f;
            __half* dst = (n < 128) ? p0 : ((n < 256) ? p1 : p2);
            int e = n & 127, hh = e >> 6, dh = e & 63;
            *(uint32_t*)&dst[((size_t)(b0i*2 + hh)*2048 + s0i)*64 + dh] =
                pack_f16(v01*sc, v00*sc);
            *(uint32_t*)&dst[((size_t)(b1i*2 + hh)*2048 + s1i)*64 + dh] =
                pack_f16(v11*sc, v10*sc);
        }
    }
}

// ============ fused out-proj + FFN (R12 128-row config) ======================
__global__ void __launch_bounds__(256) oproj_ffn(
    const __half* __restrict__ ctxh, const float* __restrict__ x,
    const __half* __restrict__ Wo, const __half* __restrict__ W1,
    const __half* __restrict__ W2, const float* __restrict__ bo,
    const float* __restrict__ b1, const float* __restrict__ b2,
    float* __restrict__ out)
{
    extern __shared__ uint4 dsm[];
    uint4* Ab = dsm;           // ctx tile, later x2h tile
    uint4* Wb = dsm + 2048;    // weight double buffer
    uint4* Hs = dsm + 4096;    // 128 rows x 32 chunks = h tile
    __half* Hsh = (__half*)Hs;

    int m0 = blockIdx.x * 128;
    int tid = threadIdx.x;
    int w = tid >> 5, lane = tid & 31, g = lane >> 2, tg = lane & 3;
    int wm = w >> 1, wn = w & 1;

    int la15 = lane & 15, xq = lane & 7, cbq = lane >> 4;
    int rowk = (lane & 7) + 8*(lane >> 4);
    int cbk  = (lane >> 3) & 1;
    int xk   = rowk & 7;

    #pragma unroll
    for (int ca = 0; ca < 2; ca++)
        #pragma unroll
        for (int it = 0; it < 4; it++) {
            int i = tid + 256*it;
            int r = i >> 3, cc = i & 7;
            cpa16(&Ab[ca*1024 + r*8 + (cc ^ (r & 7))],
                  ctxh + (size_t)(m0 + r)*128 + ca*64 + cc*8);
            cpa16(&Wb[ca*1024 + r*8 + (cc ^ (r & 7))],
                  Wo + (size_t)r*128 + ca*64 + cc*8);
        }
    CP_COMMIT();
    CP_WAIT0();
    __syncthreads();

    float x2r[2][8][4];
    #pragma unroll
    for (int mt = 0; mt < 2; mt++)
        #pragma unroll
        for (int j = 0; j < 8; j++)
            #pragma unroll
            for (int i = 0; i < 4; i++) x2r[mt][j][i] = 0.f;

    #pragma unroll
    for (int ca = 0; ca < 2; ca++) {
        const uint4* Ac = Ab + ca*1024;
        const uint4* Wc = Wb + ca*1024;
        #pragma unroll
        for (int ks = 0; ks < 4; ks++) {
            uint32_t a[2][4];
            #pragma unroll
            for (int mt = 0; mt < 2; mt++)
                ldsm4(a[mt][0], a[mt][1], a[mt][2], a[mt][3],
                      Ac + (32*wm + 16*mt + la15)*8 + ((2*ks + cbq) ^ xq));
            int ck = (2*ks + cbk) ^ xk;
            #pragma unroll
            for (int J = 0; J < 4; J++) {
                uint32_t b0, b1r, b2r, b3;
                ldsm4(b0, b1r, b2r, b3, Wc + (64*wn + J*16 + rowk)*8 + ck);
                #pragma unroll
                for (int mt = 0; mt < 2; mt++) {
                    mma_f16(x2r[mt][2*J],   a[mt][0], a[mt][1], a[mt][2], a[mt][3], b0, b1r);
                    mma_f16(x2r[mt][2*J+1], a[mt][0], a[mt][1], a[mt][2], a[mt][3], b2r, b3);
                }
            }
        }
    }
    __syncthreads();

    #pragma unroll
    for (int mt = 0; mt < 2; mt++) {
        int rl0 = 32*wm + 16*mt + g;
        int rl1 = rl0 + 8;
        #pragma unroll
        for (int j = 0; j < 8; j++) {
            int n = 64*wn + 8*j + 2*tg;
            float2 bs = *(const float2*)(bo + n);
            float2 s0 = *(const float2*)(x + (size_t)(m0 + rl0)*128 + n);
            float2 s1 = *(const float2*)(x + (size_t)(m0 + rl1)*128 + n);
            x2r[mt][j][0] += bs.x + s0.x;  x2r[mt][j][1] += bs.y + s0.y;
            x2r[mt][j][2] += bs.x + s1.x;  x2r[mt][j][3] += bs.y + s1.y;
            ((uint32_t*)&Ab[wn*1024 + rl0*8 + (j ^ (rl0 & 7))])[tg] =
                pack_f16(x2r[mt][j][1], x2r[mt][j][0]);
            ((uint32_t*)&Ab[wn*1024 + rl1*8 + (j ^ (rl1 & 7))])[tg] =
                pack_f16(x2r[mt][j][3], x2r[mt][j][2]);
        }
    }
    #pragma unroll
    for (int ca = 0; ca < 2; ca++)
        #pragma unroll
        for (int it = 0; it < 4; it++) {
            int i = tid + 256*it;
            int r = i >> 3, cc = i & 7;
            cpa16(&Wb[ca*1024 + r*8 + (cc ^ (r & 7))],
                  W1 + (size_t)r*128 + ca*64 + cc*8);
        }
    CP_COMMIT();

    for (int nh = 0; nh < 2; nh++) {
        CP_WAIT0();
        __syncthreads();

        float c1[2][8][4];
        #pragma unroll
        for (int mt = 0; mt < 2; mt++)
            #pragma unroll
            for (int j = 0; j < 8; j++)
                #pragma unroll
                for (int i = 0; i < 4; i++) c1[mt][j][i] = 0.f;

        #pragma unroll
        for (int ca = 0; ca < 2; ca++) {
            const uint4* Ac = Ab + ca*1024;
            const uint4* Wc = Wb + ca*1024;
            #pragma unroll
            for (int ks = 0; ks < 4; ks++) {
                uint32_t a[2][4];
                #pragma unroll
                for (int mt = 0; mt < 2; mt++)
                    ldsm4(a[mt][0], a[mt][1], a[mt][2], a[mt][3],
                          Ac + (32*wm + 16*mt + la15)*8 + ((2*ks + cbq) ^ xq));
                int ck = (2*ks + cbk) ^ xk;
                #pragma unroll
                for (int J = 0; J < 4; J++) {
                    uint32_t b0, b1r, b2r, b3;
                    ldsm4(b0, b1r, b2r, b3, Wc + (64*wn + J*16 + rowk)*8 + ck);
                    #pragma unroll
                    for (int mt = 0; mt < 2; mt++) {
                        mma_f16(c1[mt][2*J],   a[mt][0], a[mt][1], a[mt][2], a[mt][3], b0, b1r);
                        mma_f16(c1[mt][2*J+1], a[mt][0], a[mt][1], a[mt][2], a[mt][3], b2r, b3);
                    }
                }
            }
        }
        __syncthreads();

        if (nh == 0) {
            #pragma unroll
            for (int ca = 0; ca < 2; ca++)
                #pragma unroll
                for (int it = 0; it < 4; it++) {
                    int i = tid + 256*it;
                    int r = i >> 3, cc = i & 7;
                    cpa16(&Wb[ca*1024 + r*8 + (cc ^ (r & 7))],
                          W1 + (size_t)(128 + r)*128 + ca*64 + cc*8);
                }
        } else {
            #pragma unroll
            for (int ci = 0; ci < 2; ci++)
                #pragma unroll
                for (int it = 0; it < 4; it++) {
                    int i = tid + 256*it;
                    int r = i >> 3, cc = i & 7;
                    cpa16(&Wb[ci*1024 + r*8 + (cc ^ (r & 7))],
                          W2 + (size_t)r*256 + ci*64 + cc*8);
                }
        }
        CP_COMMIT();

        #pragma unroll
        for (int mt = 0; mt < 2; mt++) {
            int r0 = 32*wm + 16*mt + g;
            int r1 = r0 + 8;
            #pragma unroll
            for (int j = 0; j < 8; j++) {
                int nl = 64*wn + 8*j + 2*tg;
                int gc = nh*128 + nl;
                float2 bs = *(const float2*)(b1 + gc);
                float f00 = 2.f*fmaxf(c1[mt][j][0] + bs.x, 0.f);
                float f01 = 2.f*fmaxf(c1[mt][j][1] + bs.y, 0.f);
                float f10 = 2.f*fmaxf(c1[mt][j][2] + bs.x, 0.f);
                float f11 = 2.f*fmaxf(c1[mt][j][3] + bs.y, 0.f);
                int ch = gc >> 3, off = gc & 7;
                int s0 = (r0*32 + ((ch & 24) | ((ch & 7) ^ (r0 & 7))))*8 + off;
                int s1 = (r1*32 + ((ch & 24) | ((ch & 7) ^ (r1 & 7))))*8 + off;
                *(uint32_t*)&Hsh[s0] = pack_f16(f01, f00);
                *(uint32_t*)&Hsh[s1] = pack_f16(f11, f10);
            }
        }
    }

    float c2[2][8][4];
    #pragma unroll
    for (int mt = 0; mt < 2; mt++)
        #pragma unroll
        for (int j = 0; j < 8; j++)
            #pragma unroll
            for (int i = 0; i < 4; i++) c2[mt][j][i] = 0.f;

    for (int cp = 0; cp < 2; cp++) {
        CP_WAIT0();
        __syncthreads();

        #pragma unroll
        for (int ci = 0; ci < 2; ci++) {
            const uint4* Wc = Wb + ci*1024;
            int ksg0 = cp*8 + ci*4;
            #pragma unroll
            for (int ks = 0; ks < 4; ks++) {
                int cg = 2*(ksg0 + ks) + cbq;
                uint32_t a[2][4];
                #pragma unroll
                for (int mt = 0; mt < 2; mt++) {
                    int r = 32*wm + 16*mt + la15;
                    ldsm4(a[mt][0], a[mt][1], a[mt][2], a[mt][3],
                          Hs + r*32 + ((cg & 24) | ((cg & 7) ^ (r & 7))));
                }
                int ck = (2*ks + cbk) ^ xk;
                #pragma unroll
                for (int J = 0; J < 4; J++) {
                    uint32_t b0, b1r, b2r, b3;
                    ldsm4(b0, b1r, b2r, b3, Wc + (64*wn + J*16 + rowk)*8 + ck);
                    #pragma unroll
                    for (int mt = 0; mt < 2; mt++) {
                        mma_f16(c2[mt][2*J],   a[mt][0], a[mt][1], a[mt][2], a[mt][3], b0, b1r);
                        mma_f16(c2[mt][2*J+1], a[mt][0], a[mt][1], a[mt][2], a[mt][3], b2r, b3);
                    }
                }
            }
        }

        if (cp == 0) {
            __syncthreads();
            #pragma unroll
            for (int ci = 0; ci < 2; ci++)
                #pragma unroll
                for (int it = 0; it < 4; it++) {
                    int i = tid + 256*it;
                    int r = i >> 3, cc = i & 7;
                    cpa16(&Wb[ci*1024 + r*8 + (cc ^ (r & 7))],
                          W2 + (size_t)r*256 + (2 + ci)*64 + cc*8);
                }
            CP_COMMIT();
        }
    }

    #pragma unroll
    for (int mt = 0; mt < 2; mt++) {
        int r0 = m0 + 32*wm + 16*mt + g;
        int r1 = r0 + 8;
        #pragma unroll
        for (int j = 0; j < 8; j++) {
            int n = 64*wn + 8*j + 2*tg;
            float2 bs = *(const float2*)(b2 + n);
            *(float2*)(out + (size_t)r0*128 + n) =
                make_float2(x2r[mt][j][0] + c2[mt][j][0] + bs.x,
                            x2r[mt][j][1] + c2[mt][j][1] + bs.y);
            *(float2*)(out + (size_t)r1*128 + n) =
                make_float2(x2r[mt][j][2] + c2[mt][j][2] + bs.x,
                            x2r[mt][j][3] + c2[mt][j][3] + bs.y);
        }
    }
}

// ================= f16 ldmatrix flash attention ==============================
// Q tile 256, K tile 128 (two 64-col sub-steps per barrier): 16 iters.
#define ONES16 0x3C003C00u

__global__ void __launch_bounds__(256, 1) attn_f16_kernel(
    const __half* __restrict__ q, const __half* __restrict__ k,
    const __half* __restrict__ v, const int* __restrict__ actions,
    __half* __restrict__ ctxh)
{
    extern __shared__ uint4 asm_[];
    uint4* Qs = asm_;          // 256 rows x 8 chunks = 2048 (32 KB)
    uint4* Ks = asm_ + 2048;   // [2][1024]  (128 kcols x 8 chunks)
    uint4* Vs = asm_ + 4096;   // [2][1024]

    int tid = threadIdx.x;
    int w = tid >> 5, lane = tid & 31;
    int g = lane >> 2, tg = lane & 3;
    int bh = blockIdx.y, b = bh >> 1, h = bh & 1;
    int q0 = blockIdx.x * 256;

    const uint4* qg = (const uint4*)(q + ((size_t)bh * S_ + q0) * 64);
    #pragma unroll
    for (int it = 0; it < 8; it++) {
        int i = tid + 256*it;
        int r = i >> 3, cc = i & 7;
        Qs[r*8 + (cc ^ (r & 7))] = qg[i];
    }

    int rq[4];
    rq[0] = q0 + 32*w + g; rq[1] = rq[0] + 8;
    rq[2] = rq[0] + 16;    rq[3] = rq[0] + 24;
    int aq[4];
    uint32_t nw[4][4];
    const uint32_t* mr[4];
    #pragma unroll
    for (int i = 0; i < 4; i++) {
        aq[i] = (actions[b*S_ + rq[i]] == 0);
        mr[i] = g_mask + rq[i]*64;
        #pragma unroll
        for (int ww = 0; ww < 4; ww++) nw[i][ww] = mr[i][ww];
    }

    const uint4* kg = (const uint4*)(k + (size_t)bh * S_ * 64);
    const uint4* vg = (const uint4*)(v + (size_t)bh * S_ * 64);

    // tile fill: row fr (0..127), chunks 4*fh..4*fh+3 (swizzled)
    int fr = tid >> 1, fh = tid & 1;
    int xf = fr & 7;
    int sx[4];
    #pragma unroll
    for (int i = 0; i < 4; i++) sx[i] = fr*8 + ((4*fh + i) ^ xf);

    #pragma unroll
    for (int i = 0; i < 4; i++) {
        cpa16(&Ks[sx[i]], kg + (size_t)fr*8 + 4*fh + i);
        cpa16(&Vs[sx[i]], vg + (size_t)fr*8 + 4*fh + i);
    }
    CP_COMMIT();
    __syncthreads();

    int cbq = lane >> 4;
    uint32_t qf[2][4][4];
    #pragma unroll
    for (int mt = 0; mt < 2; mt++) {
        int rowq = 32*w + 16*mt + (lane & 7) + 8*((lane >> 3) & 1);
        int xq = rowq & 7;
        #pragma unroll
        for (int ks = 0; ks < 4; ks++)
            ldsm4(qf[mt][ks][0], qf[mt][ks][1], qf[mt][ks][2], qf[mt][ks][3],
                  Qs + rowq*8 + ((2*ks + cbq) ^ xq));
    }

    int rowk = (lane & 7) + 8*(lane >> 4);
    int cbk  = (lane >> 3) & 1;
    int xk   = rowk & 7;
    int rv   = (lane & 7) + 8*((lane >> 3) & 1);
    int cv   = lane >> 4;
    int xv   = lane & 7;

    float o[2][8][4];
    #pragma unroll
    for (int mt = 0; mt < 2; mt++)
        #pragma unroll
        for (int j = 0; j < 8; j++)
            #pragma unroll
            for (int i = 0; i < 4; i++) o[mt][j][i] = 0.f;
    float o9[2][4] = {{0.f,0.f,0.f,0.f},{0.f,0.f,0.f,0.f}};

    for (int kt = 0; kt < 16; kt++) {
        CP_WAIT0();
        __syncthreads();
        int cur = kt & 1;
        if (kt < 15) {
            int kn = (kt + 1) * 128, nb = cur ^ 1;
            #pragma unroll
            for (int i = 0; i < 4; i++) {
                cpa16(&Ks[nb*1024 + sx[i]], kg + (size_t)(kn + fr)*8 + 4*fh + i);
                cpa16(&Vs[nb*1024 + sx[i]], vg + (size_t)(kn + fr)*8 + 4*fh + i);
            }
            CP_COMMIT();
        }

        #pragma unroll
        for (int sub = 0; sub < 2; sub++) {
            const uint4* akrow  = Ks + cur*1024 + sub*512 + rowk*8;
            const uint4* avbase = Vs + cur*1024 + sub*512;

            // ---- S = Q K^T (64 cols) ----
            float c[2][8][4];
            #pragma unroll
            for (int mt = 0; mt < 2; mt++)
                #pragma unroll
                for (int j = 0; j < 8; j++)
                    #pragma unroll
                    for (int i = 0; i < 4; i++) c[mt][j][i] = 0.f;
            #pragma unroll
            for (int ks = 0; ks < 4; ks++) {
                int ck = (2*ks + cbk) ^ xk;
                #pragma unroll
                for (int J = 0; J < 4; J++) {
                    uint32_t b0, b1, b2, b3;
                    ldsm4(b0, b1, b2, b3, akrow + J*128 + ck);
                    #pragma unroll
                    for (int mt = 0; mt < 2; mt++) {
                        mma_f16(c[mt][2*J],   qf[mt][ks][0], qf[mt][ks][1],
                                qf[mt][ks][2], qf[mt][ks][3], b0, b1);
                        mma_f16(c[mt][2*J+1], qf[mt][ks][0], qf[mt][ks][1],
                                qf[mt][ks][2], qf[mt][ks][3], b2, b3);
                    }
                }
            }

            // ---- masked exp -> packed PV A-fragments ----
            uint32_t pj[2][2][8];
            #pragma unroll
            for (int mt = 0; mt < 2; mt++) {
                int i0 = 2*mt, i1 = 2*mt + 1;
                uint32_t w00 = aq[i0] ? (nw[i0][2*sub]   >> (2*tg)) : 0u;
                uint32_t w01 = aq[i0] ? (nw[i0][2*sub+1] >> (2*tg)) : 0u;
                uint32_t w10 = aq[i1] ? (nw[i1][2*sub]   >> (2*tg)) : 0u;
                uint32_t w11 = aq[i1] ? (nw[i1][2*sub+1] >> (2*tg)) : 0u;
                #pragma unroll
                for (int j = 0; j < 8; j++) {
                    uint32_t m0 = (j < 4) ? w00 : w01;
                    uint32_t m1 = (j < 4) ? w10 : w11;
                    int sh = 8*(j & 3);
                    uint32_t bt0 = m0 >> sh, bt1 = m1 >> sh;
                    float s00 = (bt0 & 1u) ? -100.f : c[mt][j][0];
                    float s01 = (bt0 & 2u) ? -100.f : c[mt][j][1];
                    float s10 = (bt1 & 1u) ? -100.f : c[mt][j][2];
                    float s11 = (bt1 & 2u) ? -100.f : c[mt][j][3];
                    pj[mt][0][j] = ex2h2(pack_f16(s01, s00));
                    pj[mt][1][j] = ex2h2(pack_f16(s11, s10));
                }
            }

            // ---- O += P V ; l += P * ones ----
            #pragma unroll
            for (int ks = 0; ks < 4; ks++) {
                #pragma unroll
                for (int mt = 0; mt < 2; mt++)
                    mma_f16(o9[mt], pj[mt][0][2*ks], pj[mt][1][2*ks],
                            pj[mt][0][2*ks+1], pj[mt][1][2*ks+1], ONES16, ONES16);
                #pragma unroll
                for (int J = 0; J < 4; J++) {
                    uint32_t b0, b1, b2, b3;
                    ldsm4_t(b0, b1, b2, b3,
                            avbase + (16*ks + rv)*8 + ((2*J + cv) ^ xv));
                    #pragma unroll
                    for (int mt = 0; mt < 2; mt++) {
                        mma_f16(o[mt][2*J],   pj[mt][0][2*ks], pj[mt][1][2*ks],
                                pj[mt][0][2*ks+1], pj[mt][1][2*ks+1], b0, b1);
                        mma_f16(o[mt][2*J+1], pj[mt][0][2*ks], pj[mt][1][2*ks],
                                pj[mt][0][2*ks+1], pj[mt][1][2*ks+1], b2, b3);
                    }
                }
            }
        }

        if (kt < 15) {
            #pragma unroll
            for (int i = 0; i < 4; i++)
                #pragma unroll
                for (int ww = 0; ww < 4; ww++)
                    nw[i][ww] = mr[i][(kt + 1)*4 + ww];
        }
    }

    #pragma unroll
    for (int mt = 0; mt < 2; mt++) {
        float inv0 = 1.0f / o9[mt][0];
        float inv1 = 1.0f / o9[mt][2];
        __half* og0 = ctxh + ((size_t)b*S_ + rq[2*mt])*128 + h*64;
        __half* og1 = ctxh + ((size_t)b*S_ + rq[2*mt+1])*128 + h*64;
        #pragma unroll
        for (int j = 0; j < 8; j++) {
            int c0 = 8*j + 2*tg;
            *(uint32_t*)(og0 + c0) = pack_f16(o[mt][j][1]*inv0, o[mt][j][0]*inv0);
            *(uint32_t*)(og1 + c0) = pack_f16(o[mt][j][3]*inv1, o[mt][j][2]*inv1);
        }
    }
}

// ---------------- launcher ---------------------------------------------------
extern "C" void kernel_launch(void* const* d_in, const int* in_sizes, int n_in,
                              void* d_out, int out_size)
{
    const float* x    = (const float*)d_in[0];
    const float* emb  = (const float*)d_in[1];
    const int*   act  = (const int*)  d_in[2];
    const int*   node = (const int*)  d_in[3];
    const float* Wqkv = (const float*)d_in[4];
    const float* bqkv = (const float*)d_in[5];
    const float* Wo   = (const float*)d_in[6];
    const float* bo   = (const float*)d_in[7];
    const float* lng  = (const float*)d_in[8];
    const float* lnb  = (const float*)d_in[9];
    const float* W1   = (const float*)d_in[10];
    const float* b1   = (const float*)d_in[11];
    const float* W2   = (const float*)d_in[12];
    const float* b2   = (const float*)d_in[13];
    float* out = (float*)d_out;

    __half *qkh, *vh, *qp, *kp, *vp, *ctxh, *wh;
    cudaGetSymbolAddress((void**)&qkh,  g_qk_h);
    cudaGetSymbolAddress((void**)&vh,   g_v_h);
    cudaGetSymbolAddress((void**)&qp,   g_q);
    cudaGetSymbolAddress((void**)&kp,   g_k);
    cudaGetSymbolAddress((void**)&vp,   g_v);
    cudaGetSymbolAddress((void**)&ctxh, g_ctx_h);
    cudaGetSymbolAddress((void**)&wh,   g_wh);

    cudaFuncSetAttribute(qkv_gemm,  cudaFuncAttributeMaxDynamicSharedMemorySize, 65536);
    cudaFuncSetAttribute(oproj_ffn, cudaFuncAttributeMaxDynamicSharedMemorySize, 131072);
    cudaFuncSetAttribute(attn_f16_kernel, cudaFuncAttributeMaxDynamicSharedMemorySize, 98304);

    setup_kernel<<<2432, 256>>>(x, emb, lng, lnb, node, Wqkv, Wo, W1, W2);

    qkv_gemm<<<dim3(ROWS/128, 3), 256, 65536>>>(
        qkh, vh, wh + WOFF_QKV, bqkv, qp, kp, vp);

    attn_f16_kernel<<<dim3(S_/256, 16), 256, 98304>>>(qp, kp, vp, act, ctxh);

    oproj_ffn<<<ROWS/128, 256, 131072>>>(
        ctxh, x, wh + WOFF_O, wh + WOFF_1, wh + WOFF_2, bo, b1, b2, out);
}

// round 16
// speedup vs baseline: 1.0626x; 1.0626x over previous
#include <cuda_runtime.h>
#include <cuda_fp16.h>
#include <cstdint>

#define B_   8
#define S_   2048
#define D_   128
#define ROWS (B_*S_)            // 16384
#define QSCALE 0.18033688011112042f   // log2(e)/8

// ---------------- scratch (static device memory; no allocation) -------------
__device__ __half g_qk_h[ROWS*D_];          // LN(x+emb) f16
__device__ __half g_v_h [ROWS*D_];          // LN(x) f16
__device__ __half g_q[16*S_*64];            // (b,h,s,dh), pre-scaled by log2e/8
__device__ __half g_k[16*S_*64];            // (b,h,s,dh)
__device__ __half g_v[16*S_*64];            // (b,h,s,dh)  (trans-loaded in attn)
__device__ __half g_ctx_h[ROWS*D_];         // attention out, f16
__device__ uint32_t g_mask[S_*64];          // pair mask bits: [q][k>>5] bit (k&31)
__device__ __half g_wh[131072];             // f16 weights: qkv | out | l1 | l2

#define WOFF_QKV 0
#define WOFF_O   49152
#define WOFF_1   65536
#define WOFF_2   98304

// ---------------- helpers ----------------------------------------------------
__device__ __forceinline__ uint32_t pack_f16(float hi, float lo) {
    uint32_t d;
    asm("cvt.rn.f16x2.f32 %0, %1, %2;" : "=r"(d) : "f"(hi), "f"(lo));
    return d;
}
__device__ __forceinline__ uint32_t ex2h2(uint32_t x) {
    asm("ex2.approx.f16x2 %0, %0;" : "+r"(x));
    return x;
}
__device__ __forceinline__ void mma_f16(float* d, uint32_t a0, uint32_t a1,
                                        uint32_t a2, uint32_t a3,
                                        uint32_t b0, uint32_t b1) {
    asm volatile("mma.sync.aligned.m16n8k16.row.col.f32.f16.f16.f32 "
        "{%0,%1,%2,%3}, {%4,%5,%6,%7}, {%8,%9}, {%0,%1,%2,%3};"
        : "+f"(d[0]), "+f"(d[1]), "+f"(d[2]), "+f"(d[3])
        : "r"(a0), "r"(a1), "r"(a2), "r"(a3), "r"(b0), "r"(b1));
}
__device__ __forceinline__ void ldsm4(uint32_t& r0, uint32_t& r1,
                                      uint32_t& r2, uint32_t& r3,
                                      const void* p) {
    uint32_t a = (uint32_t)__cvta_generic_to_shared(p);
    asm volatile("ldmatrix.sync.aligned.m8n8.x4.shared.b16 {%0,%1,%2,%3}, [%4];"
        : "=r"(r0), "=r"(r1), "=r"(r2), "=r"(r3) : "r"(a));
}
__device__ __forceinline__ void ldsm4_t(uint32_t& r0, uint32_t& r1,
                                        uint32_t& r2, uint32_t& r3,
                                        const void* p) {
    uint32_t a = (uint32_t)__cvta_generic_to_shared(p);
    asm volatile("ldmatrix.sync.aligned.m8n8.x4.trans.shared.b16 {%0,%1,%2,%3}, [%4];"
        : "=r"(r0), "=r"(r1), "=r"(r2), "=r"(r3) : "r"(a));
}
__device__ __forceinline__ void cpa16(void* sdst, const void* gsrc) {
    uint32_t s = (uint32_t)__cvta_generic_to_shared(sdst);
    asm volatile("cp.async.cg.shared.global [%0], [%1], 16;"
                 :: "r"(s), "l"(gsrc) : "memory");
}
#define CP_COMMIT() asm volatile("cp.async.commit_group;" ::: "memory")
#define CP_WAIT0()  asm volatile("cp.async.wait_group 0;" ::: "memory")

// ---------------- fused setup: weight cvt + mask bitmatrix + dual LN ---------
// grid 2432: [0,2048) ln, [2048,2304) mask, [2304,2432) weight cvt
__global__ void __launch_bounds__(256) setup_kernel(
    const float* __restrict__ x, const float* __restrict__ emb,
    const float* __restrict__ lng, const float* __restrict__ lnb,
    const int* __restrict__ nodeT,
    const float* __restrict__ wqkv, const float* __restrict__ wo,
    const float* __restrict__ w1,   const float* __restrict__ w2)
{
    __shared__ int smac[2048];
    __shared__ int sjob[2048];
    int bid = blockIdx.x;
    int tid = threadIdx.x;

    if (bid < 2048) {
        // ---- dual LayerNorm, 8 rows/block ----
        int row  = bid * 8 + (tid >> 5);
        int lane = tid & 31;
        size_t base = (size_t)row * 32 + lane;

        float4 xv = ((const float4*)x)[base];
        float4 ev = ((const float4*)emb)[base];
        float4 g4 = ((const float4*)lng)[lane];
        float4 b4 = ((const float4*)lnb)[lane];

        float4 t = make_float4(xv.x+ev.x, xv.y+ev.y, xv.z+ev.z, xv.w+ev.w);
        float s = t.x + t.y + t.z + t.w;
        #pragma unroll
        for (int o = 16; o; o >>= 1) s += __shfl_xor_sync(0xffffffffu, s, o);
        float mu = s * (1.0f/128.0f);
        float dx = t.x-mu, dy = t.y-mu, dz = t.z-mu, dw = t.w-mu;
        float v2 = dx*dx + dy*dy + dz*dz + dw*dw;
        #pragma unroll
        for (int o = 16; o; o >>= 1) v2 += __shfl_xor_sync(0xffffffffu, v2, o);
        float r = rsqrtf(v2 * (1.0f/128.0f) + 1e-5f);
        ((uint2*)g_qk_h)[base] = make_uint2(
            pack_f16(dy*r*g4.y + b4.y, dx*r*g4.x + b4.x),
            pack_f16(dw*r*g4.w + b4.w, dz*r*g4.z + b4.z));

        s = xv.x + xv.y + xv.z + xv.w;
        #pragma unroll
        for (int o = 16; o; o >>= 1) s += __shfl_xor_sync(0xffffffffu, s, o);
        mu = s * (1.0f/128.0f);
        dx = xv.x-mu; dy = xv.y-mu; dz = xv.z-mu; dw = xv.w-mu;
        v2 = dx*dx + dy*dy + dz*dz + dw*dw;
        #pragma unroll
        for (int o = 16; o; o >>= 1) v2 += __shfl_xor_sync(0xffffffffu, v2, o);
        r = rsqrtf(v2 * (1.0f/128.0f) + 1e-5f);
        ((uint2*)g_v_h)[base] = make_uint2(
            pack_f16(dy*r*g4.y + b4.y, dx*r*g4.x + b4.x),
            pack_f16(dw*r*g4.w + b4.w, dz*r*g4.z + b4.z));
    } else if (bid < 2304) {
        // ---- pair-mask bitmatrix, 8 q-rows/block ----
        for (int i = tid; i < 2048; i += 256) {
            smac[i] = nodeT[i*3 + 2];
            sjob[i] = nodeT[i*3 + 0];
        }
        __syncthreads();
        int w = tid >> 5, lane = tid & 31;
        int qr = (bid - 2048) * 8 + w;
        int mq = smac[qr], jq = sjob[qr];
        for (int wd = 0; wd < 64; wd++) {
            int kk = wd*32 + lane;
            int bit = (mq != smac[kk]) & (jq != sjob[kk]);
            uint32_t word = __ballot_sync(0xffffffffu, bit);
            if (lane == 0) g_mask[qr*64 + wd] = word;
        }
    } else {
        // ---- f16 weight conversion, 4 elems/thread ----
        int i = ((bid - 2304)*256 + tid) * 4;
        const float* src; int off;
        if (i < 49152)       { src = wqkv; off = i; }
        else if (i < 65536)  { src = wo;   off = i - 49152; }
        else if (i < 98304)  { src = w1;   off = i - 65536; }
        else                 { src = w2;   off = i - 98304; }
        float4 t = *(const float4*)(src + off);
        *(uint2*)&g_wh[i] = make_uint2(pack_f16(t.y, t.x), pack_f16(t.w, t.z));
    }
}

// ================= f16 QKV GEMM ==============================================
__global__ void __launch_bounds__(256, 2) qkv_gemm(
    const __half* __restrict__ A, const __half* __restrict__ A2,
    const __half* __restrict__ W, const float* __restrict__ bias,
    __half* __restrict__ p0, __half* __restrict__ p1, __half* __restrict__ p2)
{
    extern __shared__ uint4 dsm[];
    uint4* As = dsm;          // [2][1024]
    uint4* Ws = dsm + 2048;   // [2][1024]

    const int K = 128;
    int m0 = blockIdx.x * 128, n0 = blockIdx.y * 128;
    int tid = threadIdx.x;
    int w = tid >> 5, lane = tid & 31, g = lane >> 2, tg = lane & 3;
    int wm = w >> 1, wn = w & 1;

    const __half* Asrc = (blockIdx.y == 2) ? A2 : A;

    float c[2][8][4];
    #pragma unroll
    for (int mt = 0; mt < 2; mt++)
        #pragma unroll
        for (int j = 0; j < 8; j++)
            #pragma unroll
            for (int i = 0; i < 4; i++) c[mt][j][i] = 0.f;

    #pragma unroll
    for (int it = 0; it < 4; it++) {
        int i = tid + 256*it;
        int r = i >> 3, cc = i & 7;
        int sd = r*8 + (cc ^ (r & 7));
        cpa16(&As[sd], Asrc + (size_t)(m0 + r)*K + cc*8);
        cpa16(&Ws[sd], W    + (size_t)(n0 + r)*K + cc*8);
    }
    CP_COMMIT();

    int la15 = lane & 15, xq = lane & 7, cbq = lane >> 4;
    int rowk = (lane & 7) + 8*(lane >> 4);
    int cbk  = (lane >> 3) & 1;
    int xk   = rowk & 7;

    for (int ic = 0; ic < 2; ic++) {
        CP_WAIT0();
        __syncthreads();
        int cur = ic & 1;
        if (ic == 0) {
            #pragma unroll
            for (int it = 0; it < 4; it++) {
                int i = tid + 256*it;
                int r = i >> 3, cc = i & 7;
                int sd = 1024 + r*8 + (cc ^ (r & 7));
                cpa16(&As[sd], Asrc + (size_t)(m0 + r)*K + 64 + cc*8);
                cpa16(&Ws[sd], W    + (size_t)(n0 + r)*K + 64 + cc*8);
            }
            CP_COMMIT();
        }
        const uint4* Ac = As + cur*1024;
        const uint4* Wc = Ws + cur*1024;

        #pragma unroll
        for (int ks = 0; ks < 4; ks++) {
            uint32_t a[2][4];
            #pragma unroll
            for (int mt = 0; mt < 2; mt++)
                ldsm4(a[mt][0], a[mt][1], a[mt][2], a[mt][3],
                      Ac + (32*wm + 16*mt + la15)*8 + ((2*ks + cbq) ^ xq));
            int ck = (2*ks + cbk) ^ xk;
            #pragma unroll
            for (int J = 0; J < 4; J++) {
                uint32_t b0, b1, b2, b3;
                ldsm4(b0, b1, b2, b3, Wc + (64*wn + J*16 + rowk)*8 + ck);
                #pragma unroll
                for (int mt = 0; mt < 2; mt++) {
                    mma_f16(c[mt][2*J],   a[mt][0], a[mt][1], a[mt][2], a[mt][3], b0, b1);
                    mma_f16(c[mt][2*J+1], a[mt][0], a[mt][1], a[mt][2], a[mt][3], b2, b3);
                }
            }
        }
    }

    #pragma unroll
    for (int mt = 0; mt < 2; mt++) {
        int r0 = m0 + 32*wm + 16*mt + g;
        int r1 = r0 + 8;
        #pragma unroll
        for (int j = 0; j < 8; j++) {
            int n = n0 + 64*wn + 8*j + 2*tg;
            float2 bs = *(const float2*)(bias + n);
            float v00 = c[mt][j][0] + bs.x, v01 = c[mt][j][1] + bs.y;
            float v10 = c[mt][j][2] + bs.x, v11 = c[mt][j][3] + bs.y;
            int b0i = r0 >> 11, s0i = r0 & 2047;
            int b1i = r1 >> 11, s1i = r1 & 2047;
            float sc = (n < 128) ? QSCALE : 1.f;
            __half* dst = (n < 128) ? p0 : ((n < 256) ? p1 : p2);
            int e = n & 127, hh = e >> 6, dh = e & 63;
            *(uint32_t*)&dst[((size_t)(b0i*2 + hh)*2048 + s0i)*64 + dh] =
                pack_f16(v01*sc, v00*sc);
            *(uint32_t*)&dst[((size_t)(b1i*2 + hh)*2048 + s1i)*64 + dh] =
                pack_f16(v11*sc, v10*sc);
        }
    }
}

// ============ fused out-proj + FFN ==========================================
// out = x2 + 2relu(x2 W1^T + b1) W2^T + b2,  x2 = x + ctx Wo^T + bo
// x2 lives in REGISTERS between stages; f16 x2 staged into the freed ctx smem
// slot for FFN1 A-input. smem: Ab 32KB | Wb 32KB | Hs 64KB = 128KB.
__global__ void __launch_bounds__(256) oproj_ffn(
    const __half* __restrict__ ctxh, const float* __restrict__ x,
    const __half* __restrict__ Wo, const __half* __restrict__ W1,
    const __half* __restrict__ W2, const float* __restrict__ bo,
    const float* __restrict__ b1, const float* __restrict__ b2,
    float* __restrict__ out)
{
    extern __shared__ uint4 dsm[];
    uint4* Ab = dsm;           // ctx tile, later x2h tile
    uint4* Wb = dsm + 2048;    // weight double buffer
    uint4* Hs = dsm + 4096;    // 128 rows x 32 chunks = h tile
    __half* Hsh = (__half*)Hs;

    int m0 = blockIdx.x * 128;
    int tid = threadIdx.x;
    int w = tid >> 5, lane = tid & 31, g = lane >> 2, tg = lane & 3;
    int wm = w >> 1, wn = w & 1;

    int la15 = lane & 15, xq = lane & 7, cbq = lane >> 4;
    int rowk = (lane & 7) + 8*(lane >> 4);
    int cbk  = (lane >> 3) & 1;
    int xk   = rowk & 7;

    // ---- fill ctx tile + Wo ----
    #pragma unroll
    for (int ca = 0; ca < 2; ca++)
        #pragma unroll
        for (int it = 0; it < 4; it++) {
            int i = tid + 256*it;
            int r = i >> 3, cc = i & 7;
            cpa16(&Ab[ca*1024 + r*8 + (cc ^ (r & 7))],
                  ctxh + (size_t)(m0 + r)*128 + ca*64 + cc*8);
            cpa16(&Wb[ca*1024 + r*8 + (cc ^ (r & 7))],
                  Wo + (size_t)r*128 + ca*64 + cc*8);
        }
    CP_COMMIT();
    CP_WAIT0();
    __syncthreads();

    // ---- phase A: x2 = ctx Wo^T ----
    float x2r[2][8][4];
    #pragma unroll
    for (int mt = 0; mt < 2; mt++)
        #pragma unroll
        for (int j = 0; j < 8; j++)
            #pragma unroll
            for (int i = 0; i < 4; i++) x2r[mt][j][i] = 0.f;

    #pragma unroll
    for (int ca = 0; ca < 2; ca++) {
        const uint4* Ac = Ab + ca*1024;
        const uint4* Wc = Wb + ca*1024;
        #pragma unroll
        for (int ks = 0; ks < 4; ks++) {
            uint32_t a[2][4];
            #pragma unroll
            for (int mt = 0; mt < 2; mt++)
                ldsm4(a[mt][0], a[mt][1], a[mt][2], a[mt][3],
                      Ac + (32*wm + 16*mt + la15)*8 + ((2*ks + cbq) ^ xq));
            int ck = (2*ks + cbk) ^ xk;
            #pragma unroll
            for (int J = 0; J < 4; J++) {
                uint32_t b0, b1r, b2r, b3;
                ldsm4(b0, b1r, b2r, b3, Wc + (64*wn + J*16 + rowk)*8 + ck);
                #pragma unroll
                for (int mt = 0; mt < 2; mt++) {
                    mma_f16(x2r[mt][2*J],   a[mt][0], a[mt][1], a[mt][2], a[mt][3], b0, b1r);
                    mma_f16(x2r[mt][2*J+1], a[mt][0], a[mt][1], a[mt][2], a[mt][3], b2r, b3);
                }
            }
        }
    }
    __syncthreads();   // Ab/Wb consumed

    // ---- x2 epilogue: + bo + x (residual); f16 copy into Ab ----
    #pragma unroll
    for (int mt = 0; mt < 2; mt++) {
        int rl0 = 32*wm + 16*mt + g;
        int rl1 = rl0 + 8;
        #pragma unroll
        for (int j = 0; j < 8; j++) {
            int n = 64*wn + 8*j + 2*tg;
            float2 bs = *(const float2*)(bo + n);
            float2 s0 = *(const float2*)(x + (size_t)(m0 + rl0)*128 + n);
            float2 s1 = *(const float2*)(x + (size_t)(m0 + rl1)*128 + n);
            x2r[mt][j][0] += bs.x + s0.x;  x2r[mt][j][1] += bs.y + s0.y;
            x2r[mt][j][2] += bs.x + s1.x;  x2r[mt][j][3] += bs.y + s1.y;
            ((uint32_t*)&Ab[wn*1024 + rl0*8 + (j ^ (rl0 & 7))])[tg] =
                pack_f16(x2r[mt][j][1], x2r[mt][j][0]);
            ((uint32_t*)&Ab[wn*1024 + rl1*8 + (j ^ (rl1 & 7))])[tg] =
                pack_f16(x2r[mt][j][3], x2r[mt][j][2]);
        }
    }
    // prefetch W1 rows 0..127
    #pragma unroll
    for (int ca = 0; ca < 2; ca++)
        #pragma unroll
        for (int it = 0; it < 4; it++) {
            int i = tid + 256*it;
            int r = i >> 3, cc = i & 7;
            cpa16(&Wb[ca*1024 + r*8 + (cc ^ (r & 7))],
                  W1 + (size_t)r*128 + ca*64 + cc*8);
        }
    CP_COMMIT();

    // ---- phase B: h = 2relu(x2 W1^T + b1), N=256 ----
    for (int nh = 0; nh < 2; nh++) {
        CP_WAIT0();
        __syncthreads();

        float c1[2][8][4];
        #pragma unroll
        for (int mt = 0; mt < 2; mt++)
            #pragma unroll
            for (int j = 0; j < 8; j++)
                #pragma unroll
                for (int i = 0; i < 4; i++) c1[mt][j][i] = 0.f;

        #pragma unroll
        for (int ca = 0; ca < 2; ca++) {
            const uint4* Ac = Ab + ca*1024;
            const uint4* Wc = Wb + ca*1024;
            #pragma unroll
            for (int ks = 0; ks < 4; ks++) {
                uint32_t a[2][4];
                #pragma unroll
                for (int mt = 0; mt < 2; mt++)
                    ldsm4(a[mt][0], a[mt][1], a[mt][2], a[mt][3],
                          Ac + (32*wm + 16*mt + la15)*8 + ((2*ks + cbq) ^ xq));
                int ck = (2*ks + cbk) ^ xk;
                #pragma unroll
                for (int J = 0; J < 4; J++) {
                    uint32_t b0, b1r, b2r, b3;
                    ldsm4(b0, b1r, b2r, b3, Wc + (64*wn + J*16 + rowk)*8 + ck);
                    #pragma unroll
                    for (int mt = 0; mt < 2; mt++) {
                        mma_f16(c1[mt][2*J],   a[mt][0], a[mt][1], a[mt][2], a[mt][3], b0, b1r);
                        mma_f16(c1[mt][2*J+1], a[mt][0], a[mt][1], a[mt][2], a[mt][3], b2r, b3);
                    }
                }
            }
        }
        __syncthreads();

        if (nh == 0) {
            #pragma unroll
            for (int ca = 0; ca < 2; ca++)
                #pragma unroll
                for (int it = 0; it < 4; it++) {
                    int i = tid + 256*it;
                    int r = i >> 3, cc = i & 7;
                    cpa16(&Wb[ca*1024 + r*8 + (cc ^ (r & 7))],
                          W1 + (size_t)(128 + r)*128 + ca*64 + cc*8);
                }
        } else {
            #pragma unroll
            for (int ci = 0; ci < 2; ci++)
                #pragma unroll
                for (int it = 0; it < 4; it++) {
                    int i = tid + 256*it;
                    int r = i >> 3, cc = i & 7;
                    cpa16(&Wb[ci*1024 + r*8 + (cc ^ (r & 7))],
                          W2 + (size_t)r*256 + ci*64 + cc*8);
                }
        }
        CP_COMMIT();

        #pragma unroll
        for (int mt = 0; mt < 2; mt++) {
            int r0 = 32*wm + 16*mt + g;
            int r1 = r0 + 8;
            #pragma unroll
            for (int j = 0; j < 8; j++) {
                int nl = 64*wn + 8*j + 2*tg;
                int gc = nh*128 + nl;
                float2 bs = *(const float2*)(b1 + gc);
                float f00 = 2.f*fmaxf(c1[mt][j][0] + bs.x, 0.f);
                float f01 = 2.f*fmaxf(c1[mt][j][1] + bs.y, 0.f);
                float f10 = 2.f*fmaxf(c1[mt][j][2] + bs.x, 0.f);
                float f11 = 2.f*fmaxf(c1[mt][j][3] + bs.y, 0.f);
                int ch = gc >> 3, off = gc & 7;
                int s0 = (r0*32 + ((ch & 24) | ((ch & 7) ^ (r0 & 7))))*8 + off;
                int s1 = (r1*32 + ((ch & 24) | ((ch & 7) ^ (r1 & 7))))*8 + off;
                *(uint32_t*)&Hsh[s0] = pack_f16(f01, f00);
                *(uint32_t*)&Hsh[s1] = pack_f16(f11, f10);
            }
        }
    }

    // ---- phase C: out = x2 + h W2^T + b2, K=256 ----
    float c2[2][8][4];
    #pragma unroll
    for (int mt = 0; mt < 2; mt++)
        #pragma unroll
        for (int j = 0; j < 8; j++)
            #pragma unroll
            for (int i = 0; i < 4; i++) c2[mt][j][i] = 0.f;

    for (int cp = 0; cp < 2; cp++) {
        CP_WAIT0();
        __syncthreads();

        #pragma unroll
        for (int ci = 0; ci < 2; ci++) {
            const uint4* Wc = Wb + ci*1024;
            int ksg0 = cp*8 + ci*4;
            #pragma unroll
            for (int ks = 0; ks < 4; ks++) {
                int cg = 2*(ksg0 + ks) + cbq;
                uint32_t a[2][4];
                #pragma unroll
                for (int mt = 0; mt < 2; mt++) {
                    int r = 32*wm + 16*mt + la15;
                    ldsm4(a[mt][0], a[mt][1], a[mt][2], a[mt][3],
                          Hs + r*32 + ((cg & 24) | ((cg & 7) ^ (r & 7))));
                }
                int ck = (2*ks + cbk) ^ xk;
                #pragma unroll
                for (int J = 0; J < 4; J++) {
                    uint32_t b0, b1r, b2r, b3;
                    ldsm4(b0, b1r, b2r, b3, Wc + (64*wn + J*16 + rowk)*8 + ck);
                    #pragma unroll
                    for (int mt = 0; mt < 2; mt++) {
                        mma_f16(c2[mt][2*J],   a[mt][0], a[mt][1], a[mt][2], a[mt][3], b0, b1r);
                        mma_f16(c2[mt][2*J+1], a[mt][0], a[mt][1], a[mt][2], a[mt][3], b2r, b3);
                    }
                }
            }
        }

        if (cp == 0) {
            __syncthreads();
            #pragma unroll
            for (int ci = 0; ci < 2; ci++)
                #pragma unroll
                for (int it = 0; it < 4; it++) {
                    int i = tid + 256*it;
                    int r = i >> 3, cc = i & 7;
                    cpa16(&Wb[ci*1024 + r*8 + (cc ^ (r & 7))],
                          W2 + (size_t)r*256 + (2 + ci)*64 + cc*8);
                }
            CP_COMMIT();
        }
    }

    // ---- final epilogue: residual from registers ----
    #pragma unroll
    for (int mt = 0; mt < 2; mt++) {
        int r0 = m0 + 32*wm + 16*mt + g;
        int r1 = r0 + 8;
        #pragma unroll
        for (int j = 0; j < 8; j++) {
            int n = 64*wn + 8*j + 2*tg;
            float2 bs = *(const float2*)(b2 + n);
            *(float2*)(out + (size_t)r0*128 + n) =
                make_float2(x2r[mt][j][0] + c2[mt][j][0] + bs.x,
                            x2r[mt][j][1] + c2[mt][j][1] + bs.y);
            *(float2*)(out + (size_t)r1*128 + n) =
                make_float2(x2r[mt][j][2] + c2[mt][j][2] + bs.x,
                            x2r[mt][j][3] + c2[mt][j][3] + bs.y);
        }
    }
}

// ================= f16 ldmatrix flash attention (Q-tile 256) =================
#define ONES16 0x3C003C00u

__global__ void __launch_bounds__(256, 1) attn_f16_kernel(
    const __half* __restrict__ q, const __half* __restrict__ k,
    const __half* __restrict__ v, const int* __restrict__ actions,
    __half* __restrict__ ctxh)
{
    extern __shared__ uint4 asm_[];
    uint4* Qs = asm_;          // 256 rows x 8 chunks = 2048 (32 KB)
    uint4* Ks = asm_ + 2048;   // [2][512]
    uint4* Vs = asm_ + 3072;   // [2][512]

    int tid = threadIdx.x;
    int w = tid >> 5, lane = tid & 31;
    int g = lane >> 2, tg = lane & 3;
    int bh = blockIdx.y, b = bh >> 1, h = bh & 1;
    int q0 = blockIdx.x * 256;

    const uint4* qg = (const uint4*)(q + ((size_t)bh * S_ + q0) * 64);
    #pragma unroll
    for (int it = 0; it < 8; it++) {
        int i = tid + 256*it;
        int r = i >> 3, cc = i & 7;
        Qs[r*8 + (cc ^ (r & 7))] = qg[i];
    }

    int rq[4];
    rq[0] = q0 + 32*w + g; rq[1] = rq[0] + 8;
    rq[2] = rq[0] + 16;    rq[3] = rq[0] + 24;
    int aq[4];
    uint32_t nw[4][2];
    const uint32_t* mr[4];
    #pragma unroll
    for (int i = 0; i < 4; i++) {
        aq[i] = (actions[b*S_ + rq[i]] == 0);
        mr[i] = g_mask + rq[i]*64;
        nw[i][0] = mr[i][0]; nw[i][1] = mr[i][1];
    }

    const uint4* kg = (const uint4*)(k + (size_t)bh * S_ * 64);
    const uint4* vg = (const uint4*)(v + (size_t)bh * S_ * 64);

    int fr = tid >> 2, fq = tid & 3;
    int sx0 = fr*8 + ((2*fq)   ^ (fr & 7));
    int sx1 = fr*8 + ((2*fq+1) ^ (fr & 7));

    cpa16(&Ks[sx0], kg + (size_t)fr*8 + 2*fq);
    cpa16(&Ks[sx1], kg + (size_t)fr*8 + 2*fq + 1);
    cpa16(&Vs[sx0], vg + (size_t)fr*8 + 2*fq);
    cpa16(&Vs[sx1], vg + (size_t)fr*8 + 2*fq + 1);
    CP_COMMIT();
    __syncthreads();

    int cbq = lane >> 4;
    uint32_t qf[2][4][4];
    #pragma unroll
    for (int mt = 0; mt < 2; mt++) {
        int rowq = 32*w + 16*mt + (lane & 7) + 8*((lane >> 3) & 1);
        int xq = rowq & 7;
        #pragma unroll
        for (int ks = 0; ks < 4; ks++)
            ldsm4(qf[mt][ks][0], qf[mt][ks][1], qf[mt][ks][2], qf[mt][ks][3],
                  Qs + rowq*8 + ((2*ks + cbq) ^ xq));
    }

    int rowk = (lane & 7) + 8*(lane >> 4);
    int cbk  = (lane >> 3) & 1;
    int xk   = rowk & 7;
    int rv   = (lane & 7) + 8*((lane >> 3) & 1);
    int cv   = lane >> 4;
    int xv   = lane & 7;

    float o[2][8][4];
    #pragma unroll
    for (int mt = 0; mt < 2; mt++)
        #pragma unroll
        for (int j = 0; j < 8; j++)
            #pragma unroll
            for (int i = 0; i < 4; i++) o[mt][j][i] = 0.f;
    float o9[2][4] = {{0.f,0.f,0.f,0.f},{0.f,0.f,0.f,0.f}};

    for (int kt = 0; kt < 32; kt++) {
        CP_WAIT0();
        __syncthreads();
        int cur = kt & 1;
        if (kt < 31) {
            int kn = (kt + 1) * 64, nb = cur ^ 1;
            cpa16(&Ks[nb*512 + sx0], kg + (size_t)(kn + fr)*8 + 2*fq);
            cpa16(&Ks[nb*512 + sx1], kg + (size_t)(kn + fr)*8 + 2*fq + 1);
            cpa16(&Vs[nb*512 + sx0], vg + (size_t)(kn + fr)*8 + 2*fq);
            cpa16(&Vs[nb*512 + sx1], vg + (size_t)(kn + fr)*8 + 2*fq + 1);
            CP_COMMIT();
        }
        const uint4* akrow = Ks + cur*512 + rowk*8;
        const uint4* avbase = Vs + cur*512;

        float c[2][8][4];
        #pragma unroll
        for (int mt = 0; mt < 2; mt++)
            #pragma unroll
            for (int j = 0; j < 8; j++)
                #pragma unroll
                for (int i = 0; i < 4; i++) c[mt][j][i] = 0.f;
        #pragma unroll
        for (int ks = 0; ks < 4; ks++) {
            int ck = (2*ks + cbk) ^ xk;
            #pragma unroll
            for (int J = 0; J < 4; J++) {
                uint32_t b0, b1, b2, b3;
                ldsm4(b0, b1, b2, b3, akrow + J*128 + ck);
                #pragma unroll
                for (int mt = 0; mt < 2; mt++) {
                    mma_f16(c[mt][2*J],   qf[mt][ks][0], qf[mt][ks][1],
                            qf[mt][ks][2], qf[mt][ks][3], b0, b1);
                    mma_f16(c[mt][2*J+1], qf[mt][ks][0], qf[mt][ks][1],
                            qf[mt][ks][2], qf[mt][ks][3], b2, b3);
                }
            }
        }

        uint32_t pj[2][2][8];
        #pragma unroll
        for (int mt = 0; mt < 2; mt++) {
            int i0 = 2*mt, i1 = 2*mt + 1;
            uint32_t w00 = aq[i0] ? (nw[i0][0] >> (2*tg)) : 0u;
            uint32_t w01 = aq[i0] ? (nw[i0][1] >> (2*tg)) : 0u;
            uint32_t w10 = aq[i1] ? (nw[i1][0] >> (2*tg)) : 0u;
            uint32_t w11 = aq[i1] ? (nw[i1][1] >> (2*tg)) : 0u;
            #pragma unroll
            for (int j = 0; j < 8; j++) {
                uint32_t m0 = (j < 4) ? w00 : w01;
                uint32_t m1 = (j < 4) ? w10 : w11;
                int sh = 8*(j & 3);
                uint32_t bt0 = m0 >> sh, bt1 = m1 >> sh;
                float s00 = (bt0 & 1u) ? -100.f : c[mt][j][0];
                float s01 = (bt0 & 2u) ? -100.f : c[mt][j][1];
                float s10 = (bt1 & 1u) ? -100.f : c[mt][j][2];
                float s11 = (bt1 & 2u) ? -100.f : c[mt][j][3];
                pj[mt][0][j] = ex2h2(pack_f16(s01, s00));
                pj[mt][1][j] = ex2h2(pack_f16(s11, s10));
            }
        }
        if (kt < 31) {
            #pragma unroll
            for (int i = 0; i < 4; i++) {
                nw[i][0] = mr[i][kt*2 + 2];
                nw[i][1] = mr[i][kt*2 + 3];
            }
        }

        #pragma unroll
        for (int ks = 0; ks < 4; ks++) {
            #pragma unroll
            for (int mt = 0; mt < 2; mt++)
                mma_f16(o9[mt], pj[mt][0][2*ks], pj[mt][1][2*ks],
                        pj[mt][0][2*ks+1], pj[mt][1][2*ks+1], ONES16, ONES16);
            #pragma unroll
            for (int J = 0; J < 4; J++) {
                uint32_t b0, b1, b2, b3;
                ldsm4_t(b0, b1, b2, b3,
                        avbase + (16*ks + rv)*8 + ((2*J + cv) ^ xv));
                #pragma unroll
                for (int mt = 0; mt < 2; mt++) {
                    mma_f16(o[mt][2*J],   pj[mt][0][2*ks], pj[mt][1][2*ks],
                            pj[mt][0][2*ks+1], pj[mt][1][2*ks+1], b0, b1);
                    mma_f16(o[mt][2*J+1], pj[mt][0][2*ks], pj[mt][1][2*ks],
                            pj[mt][0][2*ks+1], pj[mt][1][2*ks+1], b2, b3);
                }
            }
        }
    }

    #pragma unroll
    for (int mt = 0; mt < 2; mt++) {
        float inv0 = 1.0f / o9[mt][0];
        float inv1 = 1.0f / o9[mt][2];
        __half* og0 = ctxh + ((size_t)b*S_ + rq[2*mt])*128 + h*64;
        __half* og1 = ctxh + ((size_t)b*S_ + rq[2*mt+1])*128 + h*64;
        #pragma unroll
        for (int j = 0; j < 8; j++) {
            int c0 = 8*j + 2*tg;
            *(uint32_t*)(og0 + c0) = pack_f16(o[mt][j][1]*inv0, o[mt][j][0]*inv0);
            *(uint32_t*)(og1 + c0) = pack_f16(o[mt][j][3]*inv1, o[mt][j][2]*inv1);
        }
    }
}

// ---------------- launcher ---------------------------------------------------
extern "C" void kernel_launch(void* const* d_in, const int* in_sizes, int n_in,
                              void* d_out, int out_size)
{
    const float* x    = (const float*)d_in[0];
    const float* emb  = (const float*)d_in[1];
    const int*   act  = (const int*)  d_in[2];
    const int*   node = (const int*)  d_in[3];
    const float* Wqkv = (const float*)d_in[4];
    const float* bqkv = (const float*)d_in[5];
    const float* Wo   = (const float*)d_in[6];
    const float* bo   = (const float*)d_in[7];
    const float* lng  = (const float*)d_in[8];
    const float* lnb  = (const float*)d_in[9];
    const float* W1   = (const float*)d_in[10];
    const float* b1   = (const float*)d_in[11];
    const float* W2   = (const float*)d_in[12];
    const float* b2   = (const float*)d_in[13];
    float* out = (float*)d_out;

    __half *qkh, *vh, *qp, *kp, *vp, *ctxh, *wh;
    cudaGetSymbolAddress((void**)&qkh,  g_qk_h);
    cudaGetSymbolAddress((void**)&vh,   g_v_h);
    cudaGetSymbolAddress((void**)&qp,   g_q);
    cudaGetSymbolAddress((void**)&kp,   g_k);
    cudaGetSymbolAddress((void**)&vp,   g_v);
    cudaGetSymbolAddress((void**)&ctxh, g_ctx_h);
    cudaGetSymbolAddress((void**)&wh,   g_wh);

    cudaFuncSetAttribute(qkv_gemm,  cudaFuncAttributeMaxDynamicSharedMemorySize, 65536);
    cudaFuncSetAttribute(oproj_ffn, cudaFuncAttributeMaxDynamicSharedMemorySize, 131072);
    cudaFuncSetAttribute(attn_f16_kernel, cudaFuncAttributeMaxDynamicSharedMemorySize, 65536);

    setup_kernel<<<2432, 256>>>(x, emb, lng, lnb, node, Wqkv, Wo, W1, W2);

    qkv_gemm<<<dim3(ROWS/128, 3), 256, 65536>>>(
        qkh, vh, wh + WOFF_QKV, bqkv, qp, kp, vp);

    attn_f16_kernel<<<dim3(S_/256, 16), 256, 65536>>>(qp, kp, vp, act, ctxh);

    oproj_ffn<<<ROWS/128, 256, 131072>>>(
        ctxh, x, wh + WOFF_O, wh + WOFF_1, wh + WOFF_2, bo, b1, b2, out);
}